// round 13
// baseline (speedup 1.0000x reference)
#include <cuda_runtime.h>
#include <cuda_fp16.h>
#include <cstdint>

#define Tt 2048
#define Dd 512
#define BHn 16
#define QKV_ELEMS 16777216u
#define S_ELEMS   67108864u
#define MASK_ELEMS 4194304u

// ---------------- scratch (device globals) ----------------
__device__ __half g_Qh[QKV_ELEMS];
__device__ __half g_Kh[QKV_ELEMS];
__device__ __half g_Vt[QKV_ELEMS];
__device__ __half g_E [S_ELEMS];            // exp(S-4) * maskfactor
__device__ __half g_Mh[MASK_ELEMS];         // mask ? 0 : 1  (fp16)
__device__ float  g_psum[BHn * Tt * 32];    // per-(row, nblk, wn) partial sums
__device__ float  g_inv[BHn * Tt];          // 1 / row-sum

// ---------------- helpers ----------------
__device__ __forceinline__ void ldm4(unsigned* r, const void* p) {
    unsigned a = (unsigned)__cvta_generic_to_shared(p);
    asm volatile("ldmatrix.sync.aligned.m8n8.x4.shared.b16 {%0,%1,%2,%3}, [%4];"
                 : "=r"(r[0]), "=r"(r[1]), "=r"(r[2]), "=r"(r[3]) : "r"(a));
}
__device__ __forceinline__ void mmah(float* c, const unsigned* a, unsigned b0, unsigned b1) {
    asm volatile(
        "mma.sync.aligned.m16n8k16.row.col.f32.f16.f16.f32 "
        "{%0,%1,%2,%3},{%4,%5,%6,%7},{%8,%9},{%0,%1,%2,%3};\n"
        : "+f"(c[0]), "+f"(c[1]), "+f"(c[2]), "+f"(c[3])
        : "r"(a[0]), "r"(a[1]), "r"(a[2]), "r"(a[3]), "r"(b0), "r"(b1));
}
__device__ __forceinline__ void cpasync16(void* s, const void* g) {
    unsigned sa = (unsigned)__cvta_generic_to_shared(s);
    asm volatile("cp.async.cg.shared.global [%0], [%1], 16;" :: "r"(sa), "l"(g));
}
#define CP_COMMIT() asm volatile("cp.async.commit_group;" ::: "memory")
#define CP_WAIT1()  asm volatile("cp.async.wait_group 1;" ::: "memory")

// FMA-pipe exp2 (no MUFU). Valid for |y| < 2^21; rel err ~1e-5.
__device__ __forceinline__ float fexp2(float y) {
    float z  = __fadd_rn(y, 12582912.0f);
    float nf = __fadd_rn(z, -12582912.0f);
    float f  = y - nf;
    float p  = 0.0096181291f;
    p = fmaf(p, f, 0.0555041087f);
    p = fmaf(p, f, 0.2402265069f);
    p = fmaf(p, f, 0.6931471806f);
    p = fmaf(p, f, 1.0f);
    int nb = __float_as_int(z);
    float s = __int_as_float((nb - (0x4B400000 - 127)) << 23);
    return p * s;
}

// ---------------- convert Q,K to fp16 (gate & 1/sqrt(64) folded into Q) ----------------
__global__ void convert_qk(const float* __restrict__ Q, const float* __restrict__ K,
                           const float* __restrict__ route) {
    unsigned idx = blockIdx.x * 256u + threadIdx.x;       // float4 index
    unsigned i = idx * 4u;
    int d = (int)(i & (Dd - 1));
    int b = (int)(i >> 23);
    float g = route[b * 8 + (d >> 6)] * 0.125f;
    float4 q = ((const float4*)Q)[idx];
    float4 k = ((const float4*)K)[idx];
    __half2 q01 = __floats2half2_rn(q.x * g, q.y * g);
    __half2 q23 = __floats2half2_rn(q.z * g, q.w * g);
    __half2 k01 = __floats2half2_rn(k.x, k.y);
    __half2 k23 = __floats2half2_rn(k.z, k.w);
    ((__half2*)g_Qh)[idx * 2]     = q01;
    ((__half2*)g_Qh)[idx * 2 + 1] = q23;
    ((__half2*)g_Kh)[idx * 2]     = k01;
    ((__half2*)g_Kh)[idx * 2 + 1] = k23;
}

// ---------------- transpose V -> Vt fp16 ----------------
__global__ void convert_vt(const float* __restrict__ V) {
    __shared__ float tile[32][33];
    int bh = blockIdx.z, t0 = blockIdx.x * 32, d0 = blockIdx.y * 32;
    int tx = threadIdx.x & 31, ty = threadIdx.x >> 5;
    const float* Vb = V + (size_t)bh * Tt * Dd;
#pragma unroll
    for (int j = 0; j < 4; j++)
        tile[ty + j * 8][tx] = Vb[(size_t)(t0 + ty + j * 8) * Dd + d0 + tx];
    __syncthreads();
#pragma unroll
    for (int j = 0; j < 4; j++) {
        int d = d0 + ty + j * 8, tt = t0 + tx;
        g_Vt[(size_t)bh * Dd * Tt + (size_t)d * Tt + tt] = __float2half_rn(tile[tx][ty + j * 8]);
    }
}

// ---------------- mask -> multiplicative fp16 ----------------
__global__ void convert_mask(const int* __restrict__ mask) {
    unsigned idx = blockIdx.x * 256u + threadIdx.x;       // int4 index
    int4 m = ((const int4*)mask)[idx];
    __half2 a = __floats2half2_rn(m.x ? 0.f : 1.f, m.y ? 0.f : 1.f);
    __half2 b = __floats2half2_rn(m.z ? 0.f : 1.f, m.w ? 0.f : 1.f);
    ((__half2*)g_Mh)[idx * 2]     = a;
    ((__half2*)g_Mh)[idx * 2 + 1] = b;
}

// k-tile = 64; row stride 72 elems (144B, conflict-free)
#define PS 72
#define A_BYTES (128 * PS * 2)              // 18432
#define G_A 0
#define G_B (A_BYTES)
#define G_STAGE (2 * A_BYTES)               // 36864
#define NSTAGE 3
#define G_SMEM (NSTAGE * G_STAGE)           // 110592

// ---------------- GEMM1: E = exp(Qg*K^T - 4)*maskf, + partial row sums ----------------
// CTA 128x128x64, 256 threads, 2 CTAs/SM
__global__ __launch_bounds__(256, 2) void gemm1() {
    constexpr int lda = Dd, KT = Dd / 64;
    extern __shared__ __align__(16) char sm[];

    const int bh = blockIdx.z;
    const int m0 = blockIdx.y * 128;
    const int n0 = blockIdx.x * 128;
    const int t = threadIdx.x, lane = t & 31, warp = t >> 5;
    const int wm = warp & 3, wn = warp >> 2;     // 4x2 warps, warp tile 32x64
    const int lrow = lane & 15, lko = (lane >> 4) << 3;

    const __half* gA = g_Qh + (size_t)bh * Tt * lda + (size_t)m0 * lda;
    const __half* gB = g_Kh + (size_t)bh * Tt * lda + (size_t)n0 * lda;

    // loads: row = t>>1 (0..127), 64B half = (t&1)
    const size_t goff = (size_t)(t >> 1) * lda + (t & 1) * 32;
    const int    soff = (t >> 1) * (PS * 2) + (t & 1) * 64;

    float acc[2][8][4];
#pragma unroll
    for (int a = 0; a < 2; a++)
#pragma unroll
        for (int b = 0; b < 8; b++)
#pragma unroll
            for (int c = 0; c < 4; c++) acc[a][b][c] = 0.f;

#pragma unroll
    for (int p = 0; p < 2; p++) {
        char* stg = sm + p * G_STAGE;
        const size_t ko = (size_t)p * 64;
#pragma unroll
        for (int j = 0; j < 4; j++) {
            cpasync16(stg + G_A + soff + j * 16, gA + goff + ko + j * 8);
            cpasync16(stg + G_B + soff + j * 16, gB + goff + ko + j * 8);
        }
        CP_COMMIT();
    }

    int sc = 0, sp = 2;     // compute stage, prefetch stage (mod 3)
    for (int kt = 0; kt < KT; kt++) {
        CP_WAIT1();
        __syncthreads();
        if (kt + 2 < KT) {
            char* stg = sm + sp * G_STAGE;
            const size_t ko = (size_t)(kt + 2) * 64;
#pragma unroll
            for (int j = 0; j < 4; j++) {
                cpasync16(stg + G_A + soff + j * 16, gA + goff + ko + j * 8);
                cpasync16(stg + G_B + soff + j * 16, gB + goff + ko + j * 8);
            }
        }
        CP_COMMIT();

        char* stg = sm + sc * G_STAGE;
        unsigned short* sA = (unsigned short*)(stg + G_A);
        unsigned short* sB = (unsigned short*)(stg + G_B);

#pragma unroll
        for (int ks = 0; ks < 4; ks++) {
            int kb = ks * 16 + lko;
            unsigned af[2][4], bf[4][4];
            ldm4(af[0], &sA[(wm * 32      + lrow) * PS + kb]);
            ldm4(af[1], &sA[(wm * 32 + 16 + lrow) * PS + kb]);
#pragma unroll
            for (int nb = 0; nb < 4; nb++)
                ldm4(bf[nb], &sB[(wn * 64 + nb * 16 + lrow) * PS + kb]);
#pragma unroll
            for (int mt = 0; mt < 2; mt++)
#pragma unroll
                for (int nt = 0; nt < 8; nt++) {
                    int nb = nt >> 1, o = nt & 1;
                    mmah(acc[mt][nt], af[mt], bf[nb][o], bf[nb][o + 2]);
                }
        }
        sc = (sc == 2) ? 0 : sc + 1;
        sp = (sp == 2) ? 0 : sp + 1;
    }

    // epilogue: masked exp(S-4) -> fp16 E, plus per-row partial sums
    const float L2E = 1.44269504f;
    const float SH  = -5.77078016f;
    __half* Ep = g_E + (size_t)bh * Tt * Tt;
    int rbase = m0 + wm * 32 + (lane >> 2);
    int cbase = n0 + wn * 64 + (lane & 3) * 2;
    float sums[4] = {0.f, 0.f, 0.f, 0.f};
#pragma unroll
    for (int mt = 0; mt < 2; mt++) {
        int r0 = rbase + mt * 16;
#pragma unroll
        for (int nt = 0; nt < 8; nt++) {
            int c = cbase + nt * 8;
            __half2 mh0 = *(const __half2*)&g_Mh[(size_t)r0       * Tt + c];
            __half2 mh1 = *(const __half2*)&g_Mh[(size_t)(r0 + 8) * Tt + c];
            float2 mf0 = __half22float2(mh0);
            float2 mf1 = __half22float2(mh1);
            float e0 = fexp2(fmaf(acc[mt][nt][0], L2E, SH)) * mf0.x;
            float e1 = fexp2(fmaf(acc[mt][nt][1], L2E, SH)) * mf0.y;
            float e2 = fexp2(fmaf(acc[mt][nt][2], L2E, SH)) * mf1.x;
            float e3 = fexp2(fmaf(acc[mt][nt][3], L2E, SH)) * mf1.y;
            sums[mt * 2]     += e0 + e1;
            sums[mt * 2 + 1] += e2 + e3;
            *(__half2*)&Ep[(size_t)r0       * Tt + c] = __floats2half2_rn(e0, e1);
            *(__half2*)&Ep[(size_t)(r0 + 8) * Tt + c] = __floats2half2_rn(e2, e3);
        }
    }

    // reduce across the 4 lanes sharing a row; write partials straight to gmem
#pragma unroll
    for (int j = 0; j < 4; j++) {
        float v = sums[j];
        v += __shfl_xor_sync(0xFFFFFFFFu, v, 1);
        v += __shfl_xor_sync(0xFFFFFFFFu, v, 2);
        sums[j] = v;
    }
    if ((lane & 3) == 0) {
        int slot = blockIdx.x * 2 + wn;           // 0..31
#pragma unroll
        for (int j = 0; j < 4; j++) {
            int row = m0 + wm * 32 + (lane >> 2) + ((j & 1) ? 8 : 0) + ((j >> 1) ? 16 : 0);
            g_psum[((size_t)bh * Tt + row) * 32 + slot] = sums[j];
        }
    }
}

// ---------------- fold 32 partials -> 1/sum ----------------
__global__ __launch_bounds__(256) void make_inv() {
    int r = blockIdx.x * 256 + threadIdx.x;       // 0 .. 32767
    const float4* p = (const float4*)&g_psum[(size_t)r * 32];
    float tot = 0.f;
#pragma unroll
    for (int j = 0; j < 8; j++) {
        float4 v = p[j];
        tot += (v.x + v.y) + (v.z + v.w);
    }
    g_inv[r] = tot > 0.f ? 1.f / tot : 0.f;
}

// ---------------- GEMM2: out = (E * Vt^T) * inv[row] * gate ----------------
// CTA 128x128x64, 256 threads, 2 CTAs/SM
__global__ __launch_bounds__(256, 2) void gemm2(float* __restrict__ outp,
                                                const float* __restrict__ route) {
    constexpr int lda = Tt, KT = Tt / 64;
    extern __shared__ __align__(16) char sm[];

    const int bh = blockIdx.z;
    const int m0 = blockIdx.y * 128;
    const int n0 = blockIdx.x * 128;
    const int t = threadIdx.x, lane = t & 31, warp = t >> 5;
    const int wm = warp & 3, wn = warp >> 2;     // 4x2 warps, warp tile 32x64
    const int lrow = lane & 15, lko = (lane >> 4) << 3;

    const __half* gA = g_E  + (size_t)bh * Tt * lda + (size_t)m0 * lda;
    const __half* gB = g_Vt + (size_t)bh * Dd * lda + (size_t)n0 * lda;

    const size_t goff = (size_t)(t >> 1) * lda + (t & 1) * 32;
    const int    soff = (t >> 1) * (PS * 2) + (t & 1) * 64;

    float acc[2][8][4];
#pragma unroll
    for (int a = 0; a < 2; a++)
#pragma unroll
        for (int b = 0; b < 8; b++)
#pragma unroll
            for (int c = 0; c < 4; c++) acc[a][b][c] = 0.f;

#pragma unroll
    for (int p = 0; p < 2; p++) {
        char* stg = sm + p * G_STAGE;
        const size_t ko = (size_t)p * 64;
#pragma unroll
        for (int j = 0; j < 4; j++) {
            cpasync16(stg + G_A + soff + j * 16, gA + goff + ko + j * 8);
            cpasync16(stg + G_B + soff + j * 16, gB + goff + ko + j * 8);
        }
        CP_COMMIT();
    }

    int sc = 0, sp = 2;
    for (int kt = 0; kt < KT; kt++) {
        CP_WAIT1();
        __syncthreads();
        if (kt + 2 < KT) {
            char* stg = sm + sp * G_STAGE;
            const size_t ko = (size_t)(kt + 2) * 64;
#pragma unroll
            for (int j = 0; j < 4; j++) {
                cpasync16(stg + G_A + soff + j * 16, gA + goff + ko + j * 8);
                cpasync16(stg + G_B + soff + j * 16, gB + goff + ko + j * 8);
            }
        }
        CP_COMMIT();

        char* stg = sm + sc * G_STAGE;
        unsigned short* sA = (unsigned short*)(stg + G_A);
        unsigned short* sB = (unsigned short*)(stg + G_B);

#pragma unroll
        for (int ks = 0; ks < 4; ks++) {
            int kb = ks * 16 + lko;
            unsigned af[2][4], bf[4][4];
            ldm4(af[0], &sA[(wm * 32      + lrow) * PS + kb]);
            ldm4(af[1], &sA[(wm * 32 + 16 + lrow) * PS + kb]);
#pragma unroll
            for (int nb = 0; nb < 4; nb++)
                ldm4(bf[nb], &sB[(wn * 64 + nb * 16 + lrow) * PS + kb]);
#pragma unroll
            for (int mt = 0; mt < 2; mt++)
#pragma unroll
                for (int nt = 0; nt < 8; nt++) {
                    int nb = nt >> 1, o = nt & 1;
                    mmah(acc[mt][nt], af[mt], bf[nb][o], bf[nb][o + 2]);
                }
        }
        sc = (sc == 2) ? 0 : sc + 1;
        sp = (sp == 2) ? 0 : sp + 1;
    }

    float* Cp = outp + (size_t)bh * Tt * Dd;
    int rbase = m0 + wm * 32 + (lane >> 2);
    int cbase = n0 + wn * 64 + (lane & 3) * 2;
    float gsc = route[(bh >> 3) * 8 + ((n0 + wn * 64) >> 6)];
    const float* invb = g_inv + (size_t)bh * Tt;
#pragma unroll
    for (int mt = 0; mt < 2; mt++) {
        int r0 = rbase + mt * 16;
        float s0 = gsc * invb[r0];
        float s1 = gsc * invb[r0 + 8];
#pragma unroll
        for (int nt = 0; nt < 8; nt++) {
            int c = cbase + nt * 8;
            *(float2*)&Cp[(size_t)r0       * Dd + c] = make_float2(acc[mt][nt][0] * s0, acc[mt][nt][1] * s0);
            *(float2*)&Cp[(size_t)(r0 + 8) * Dd + c] = make_float2(acc[mt][nt][2] * s1, acc[mt][nt][3] * s1);
        }
    }
}

// ---------------- launch ----------------
extern "C" void kernel_launch(void* const* d_in, const int* in_sizes, int n_in,
                              void* d_out, int out_size) {
    const float* Q     = (const float*)d_in[0];
    const float* K     = (const float*)d_in[1];
    const float* V     = (const float*)d_in[2];
    const float* route = (const float*)d_in[3];
    const int*   mask  = (const int*)d_in[5];
    float* out = (float*)d_out;

    cudaFuncSetAttribute(gemm1, cudaFuncAttributeMaxDynamicSharedMemorySize, G_SMEM);
    cudaFuncSetAttribute(gemm2, cudaFuncAttributeMaxDynamicSharedMemorySize, G_SMEM);

    convert_qk<<<QKV_ELEMS / 1024, 256>>>(Q, K, route);
    convert_vt<<<dim3(Tt / 32, Dd / 32, BHn), 256>>>(V);
    convert_mask<<<MASK_ELEMS / 1024, 256>>>(mask);
    gemm1<<<dim3(Tt / 128, Tt / 128, BHn), 256, G_SMEM>>>();
    make_inv<<<BHn * Tt / 256, 256>>>();
    gemm2<<<dim3(Dd / 128, Tt / 128, BHn), 256, G_SMEM>>>(out, route);
}

// round 14
// speedup vs baseline: 1.1333x; 1.1333x over previous
#include <cuda_runtime.h>
#include <cuda_fp16.h>
#include <cstdint>

#define Tt 2048
#define Dd 512
#define BHn 16
#define QKV_ELEMS 16777216u
#define S_ELEMS   67108864u
#define MASK_ELEMS 4194304u

// ---------------- scratch (device globals) ----------------
__device__ __half g_Qh[QKV_ELEMS];
__device__ __half g_Kh[QKV_ELEMS];
__device__ __half g_Vt[QKV_ELEMS];
__device__ __half g_E [S_ELEMS];            // exp(S-4) * maskfactor
__device__ __half g_Mh[MASK_ELEMS];         // mask ? 0 : 1  (fp16)
__device__ float  g_psum[BHn * Tt * 16];    // per-(row, n-block) partial sums
__device__ float  g_inv[BHn * Tt];          // 1 / row-sum

// ---------------- helpers ----------------
__device__ __forceinline__ void ldm4(unsigned* r, const void* p) {
    unsigned a = (unsigned)__cvta_generic_to_shared(p);
    asm volatile("ldmatrix.sync.aligned.m8n8.x4.shared.b16 {%0,%1,%2,%3}, [%4];"
                 : "=r"(r[0]), "=r"(r[1]), "=r"(r[2]), "=r"(r[3]) : "r"(a));
}
__device__ __forceinline__ void mmah(float* c, const unsigned* a, unsigned b0, unsigned b1) {
    asm volatile(
        "mma.sync.aligned.m16n8k16.row.col.f32.f16.f16.f32 "
        "{%0,%1,%2,%3},{%4,%5,%6,%7},{%8,%9},{%0,%1,%2,%3};\n"
        : "+f"(c[0]), "+f"(c[1]), "+f"(c[2]), "+f"(c[3])
        : "r"(a[0]), "r"(a[1]), "r"(a[2]), "r"(a[3]), "r"(b0), "r"(b1));
}
__device__ __forceinline__ void cpasync16(void* s, const void* g) {
    unsigned sa = (unsigned)__cvta_generic_to_shared(s);
    asm volatile("cp.async.cg.shared.global [%0], [%1], 16;" :: "r"(sa), "l"(g));
}
#define CP_COMMIT() asm volatile("cp.async.commit_group;" ::: "memory")
#define CP_WAIT2()  asm volatile("cp.async.wait_group 2;" ::: "memory")

// FMA-pipe exp2 (no MUFU). Valid for |y| < 2^21; rel err ~1e-5.
__device__ __forceinline__ float fexp2(float y) {
    float z  = __fadd_rn(y, 12582912.0f);
    float nf = __fadd_rn(z, -12582912.0f);
    float f  = y - nf;
    float p  = 0.0096181291f;
    p = fmaf(p, f, 0.0555041087f);
    p = fmaf(p, f, 0.2402265069f);
    p = fmaf(p, f, 0.6931471806f);
    p = fmaf(p, f, 1.0f);
    int nb = __float_as_int(z);
    float s = __int_as_float((nb - (0x4B400000 - 127)) << 23);
    return p * s;
}

// ---------------- convert Q,K to fp16 (gate & 1/sqrt(64) folded into Q) ----------------
// 8 elems/thread (two float4 per tensor)
__global__ void convert_qk(const float* __restrict__ Q, const float* __restrict__ K,
                           const float* __restrict__ route) {
    unsigned idx = (blockIdx.x * 256u + threadIdx.x) * 2u;    // float4 index (pairs)
#pragma unroll
    for (int u = 0; u < 2; u++) {
        unsigned id4 = idx + u;
        unsigned i = id4 * 4u;
        int d = (int)(i & (Dd - 1));
        int b = (int)(i >> 23);
        float g = route[b * 8 + (d >> 6)] * 0.125f;
        float4 q = ((const float4*)Q)[id4];
        float4 k = ((const float4*)K)[id4];
        __half2 q01 = __floats2half2_rn(q.x * g, q.y * g);
        __half2 q23 = __floats2half2_rn(q.z * g, q.w * g);
        __half2 k01 = __floats2half2_rn(k.x, k.y);
        __half2 k23 = __floats2half2_rn(k.z, k.w);
        ((__half2*)g_Qh)[id4 * 2]     = q01;
        ((__half2*)g_Qh)[id4 * 2 + 1] = q23;
        ((__half2*)g_Kh)[id4 * 2]     = k01;
        ((__half2*)g_Kh)[id4 * 2 + 1] = k23;
    }
}

// ---------------- transpose V -> Vt fp16 ----------------
__global__ void convert_vt(const float* __restrict__ V) {
    __shared__ float tile[32][33];
    int bh = blockIdx.z, t0 = blockIdx.x * 32, d0 = blockIdx.y * 32;
    int tx = threadIdx.x & 31, ty = threadIdx.x >> 5;
    const float* Vb = V + (size_t)bh * Tt * Dd;
#pragma unroll
    for (int j = 0; j < 4; j++)
        tile[ty + j * 8][tx] = Vb[(size_t)(t0 + ty + j * 8) * Dd + d0 + tx];
    __syncthreads();
#pragma unroll
    for (int j = 0; j < 4; j++) {
        int d = d0 + ty + j * 8, tt = t0 + tx;
        g_Vt[(size_t)bh * Dd * Tt + (size_t)d * Tt + tt] = __float2half_rn(tile[tx][ty + j * 8]);
    }
}

// ---------------- mask -> multiplicative fp16 ----------------
__global__ void convert_mask(const int* __restrict__ mask) {
    unsigned idx = blockIdx.x * 256u + threadIdx.x;       // int4 index
    int4 m = ((const int4*)mask)[idx];
    __half2 a = __floats2half2_rn(m.x ? 0.f : 1.f, m.y ? 0.f : 1.f);
    __half2 b = __floats2half2_rn(m.z ? 0.f : 1.f, m.w ? 0.f : 1.f);
    ((__half2*)g_Mh)[idx * 2]     = a;
    ((__half2*)g_Mh)[idx * 2 + 1] = b;
}

#define PS 40

// ---------------- GEMM1: E = exp(Qg*K^T - 4)*maskf, + partial row sums ----------------
// CTA 128x256x32, 512 threads (R9-proven config)
#define G1_A 0
#define G1_B (128 * PS * 2)                 // 10240
#define G1_STAGE (G1_B + 256 * PS * 2)      // 30720
#define NSTAGE 4
#define G1_SMEM (NSTAGE * G1_STAGE)         // 122880

__global__ __launch_bounds__(512, 1) void gemm1() {
    constexpr int lda = Dd, KT = Dd / 32;
    extern __shared__ __align__(16) char sm[];

    const int bh = blockIdx.z;
    const int m0 = blockIdx.y * 128;
    const int n0 = blockIdx.x * 256;
    const int t = threadIdx.x, lane = t & 31, warp = t >> 5;
    const int wm = warp & 3, wn = warp >> 2;     // 4x4 warps, warp tile 32x64
    const int lrow = lane & 15, lko = (lane >> 4) << 3;

    const __half* gA = g_Qh + (size_t)bh * Tt * lda + (size_t)m0 * lda;
    const __half* gB = g_Kh + (size_t)bh * Tt * lda + (size_t)n0 * lda;

    const int arow = t >> 2, kc = t & 3;
    const size_t goff = (size_t)arow * lda + kc * 8;
    const int soff = arow * (PS * 2) + kc * 16;
    const size_t gstep = (size_t)128 * lda;
    const int sstep = 128 * (PS * 2);

    float acc[2][8][4];
#pragma unroll
    for (int a = 0; a < 2; a++)
#pragma unroll
        for (int b = 0; b < 8; b++)
#pragma unroll
            for (int c = 0; c < 4; c++) acc[a][b][c] = 0.f;

#pragma unroll
    for (int p = 0; p < 3; p++) {
        char* stg = sm + p * G1_STAGE;
        const size_t ko = (size_t)p * 32;
        cpasync16(stg + G1_A + soff, gA + goff + ko);
        cpasync16(stg + G1_B + soff, gB + goff + ko);
        cpasync16(stg + G1_B + soff + sstep, gB + goff + gstep + ko);
        CP_COMMIT();
    }

    for (int kt = 0; kt < KT; kt++) {
        CP_WAIT2();
        __syncthreads();
        if (kt + 3 < KT) {
            char* stg = sm + ((kt + 3) & (NSTAGE - 1)) * G1_STAGE;
            const size_t ko = (size_t)(kt + 3) * 32;
            cpasync16(stg + G1_A + soff, gA + goff + ko);
            cpasync16(stg + G1_B + soff, gB + goff + ko);
            cpasync16(stg + G1_B + soff + sstep, gB + goff + gstep + ko);
        }
        CP_COMMIT();

        char* stg = sm + (kt & (NSTAGE - 1)) * G1_STAGE;
        unsigned short* sA = (unsigned short*)(stg + G1_A);
        unsigned short* sB = (unsigned short*)(stg + G1_B);

#pragma unroll
        for (int ks = 0; ks < 2; ks++) {
            int kb = ks * 16 + lko;
            unsigned af[2][4], bf[4][4];
#pragma unroll
            for (int mt = 0; mt < 2; mt++) {
                int r = (wm * 32 + mt * 16 + lrow) * PS + kb;
                ldm4(af[mt], &sA[r]);
            }
#pragma unroll
            for (int nb = 0; nb < 4; nb++) {
                int r = (wn * 64 + nb * 16 + lrow) * PS + kb;
                ldm4(bf[nb], &sB[r]);
            }
            // nt outer, mt inner: consecutive HMMAs share the B fragment pair
#pragma unroll
            for (int nt = 0; nt < 8; nt++) {
                int nb = nt >> 1, o = nt & 1;
#pragma unroll
                for (int mt = 0; mt < 2; mt++)
                    mmah(acc[mt][nt], af[mt], bf[nb][o], bf[nb][o + 2]);
            }
        }
    }

    // epilogue: masked exp(S-4) -> fp16 E, plus per-row partial sums
    const float L2E = 1.44269504f;
    const float SH  = -5.77078016f;
    __half* Ep = g_E + (size_t)bh * Tt * Tt;
    int rbase = m0 + wm * 32 + (lane >> 2);
    int cbase = n0 + wn * 64 + (lane & 3) * 2;
    float sums[4] = {0.f, 0.f, 0.f, 0.f};
#pragma unroll
    for (int mt = 0; mt < 2; mt++) {
        int r0 = rbase + mt * 16;
#pragma unroll
        for (int nt = 0; nt < 8; nt++) {
            int c = cbase + nt * 8;
            __half2 mh0 = *(const __half2*)&g_Mh[(size_t)r0       * Tt + c];
            __half2 mh1 = *(const __half2*)&g_Mh[(size_t)(r0 + 8) * Tt + c];
            float2 mf0 = __half22float2(mh0);
            float2 mf1 = __half22float2(mh1);
            float e0 = fexp2(fmaf(acc[mt][nt][0], L2E, SH)) * mf0.x;
            float e1 = fexp2(fmaf(acc[mt][nt][1], L2E, SH)) * mf0.y;
            float e2 = fexp2(fmaf(acc[mt][nt][2], L2E, SH)) * mf1.x;
            float e3 = fexp2(fmaf(acc[mt][nt][3], L2E, SH)) * mf1.y;
            sums[mt * 2]     += e0 + e1;
            sums[mt * 2 + 1] += e2 + e3;
            *(__half2*)&Ep[(size_t)r0       * Tt + c] = __floats2half2_rn(e0, e1);
            *(__half2*)&Ep[(size_t)(r0 + 8) * Tt + c] = __floats2half2_rn(e2, e3);
        }
    }

    // reduce partial sums: lanes sharing a row, then across wn via smem
    float* ps = (float*)sm;                   // 128 rows x 4 wn
#pragma unroll
    for (int j = 0; j < 4; j++) {
        float v = sums[j];
        v += __shfl_xor_sync(0xFFFFFFFFu, v, 1);
        v += __shfl_xor_sync(0xFFFFFFFFu, v, 2);
        sums[j] = v;
    }
    __syncthreads();
    if ((lane & 3) == 0) {
        int rl = wm * 32 + (lane >> 2);
#pragma unroll
        for (int j = 0; j < 4; j++)
            ps[(rl + j * 8) * 4 + wn] = sums[j];
    }
    __syncthreads();
    if (t < 128) {
        float s4 = ps[t * 4] + ps[t * 4 + 1] + ps[t * 4 + 2] + ps[t * 4 + 3];
        g_psum[((size_t)bh * Tt + m0 + t) * 16 + blockIdx.x] = s4;
    }
}

// ---------------- fold 16 partials -> 1/sum ----------------
__global__ __launch_bounds__(256) void make_inv() {
    int r = blockIdx.x * 256 + threadIdx.x;       // 0 .. 32767
    const float4* p = (const float4*)&g_psum[(size_t)r * 16];
    float4 a = p[0], b = p[1], c = p[2], d = p[3];
    float tot = (((a.x + a.y) + (a.z + a.w)) + ((b.x + b.y) + (b.z + b.w)))
              + (((c.x + c.y) + (c.z + c.w)) + ((d.x + d.y) + (d.z + d.w)));
    g_inv[r] = tot > 0.f ? 1.f / tot : 0.f;
}

// ---------------- GEMM2: out = (E * Vt^T) * inv[row] * gate, CTA 128x128x32 ----------------
#define G2_A 0
#define G2_B (128 * PS * 2)
#define G2_STAGE (2 * 128 * PS * 2)          // 20480
#define G2_SMEM (NSTAGE * G2_STAGE)          // 81920

__global__ __launch_bounds__(512, 1) void gemm2(float* __restrict__ outp,
                                                const float* __restrict__ route) {
    constexpr int lda = Tt, KT = Tt / 32;
    extern __shared__ __align__(16) char sm[];

    const int bh = blockIdx.z;
    const int m0 = blockIdx.y * 128;
    const int n0 = blockIdx.x * 128;
    const int t = threadIdx.x, lane = t & 31, warp = t >> 5;
    const int wm = warp & 3, wn = warp >> 2;     // 4x4 warps, warp tile 32x32
    const int lrow = lane & 15, lko = (lane >> 4) << 3;

    const __half* gA = g_E  + (size_t)bh * Tt * lda + (size_t)m0 * lda;
    const __half* gB = g_Vt + (size_t)bh * Dd * lda + (size_t)n0 * lda;

    const int arow = t >> 2, kc = t & 3;
    const size_t goff = (size_t)arow * lda + kc * 8;
    const int soff = arow * (PS * 2) + kc * 16;

    float acc[2][4][4];
#pragma unroll
    for (int a = 0; a < 2; a++)
#pragma unroll
        for (int b = 0; b < 4; b++)
#pragma unroll
            for (int c = 0; c < 4; c++) acc[a][b][c] = 0.f;

#pragma unroll
    for (int p = 0; p < 3; p++) {
        char* stg = sm + p * G2_STAGE;
        const size_t ko = (size_t)p * 32;
        cpasync16(stg + G2_A + soff, gA + goff + ko);
        cpasync16(stg + G2_B + soff, gB + goff + ko);
        CP_COMMIT();
    }

    for (int kt = 0; kt < KT; kt++) {
        CP_WAIT2();
        __syncthreads();
        if (kt + 3 < KT) {
            char* stg = sm + ((kt + 3) & (NSTAGE - 1)) * G2_STAGE;
            const size_t ko = (size_t)(kt + 3) * 32;
            cpasync16(stg + G2_A + soff, gA + goff + ko);
            cpasync16(stg + G2_B + soff, gB + goff + ko);
        }
        CP_COMMIT();

        char* stg = sm + (kt & (NSTAGE - 1)) * G2_STAGE;
        unsigned short* sA = (unsigned short*)(stg + G2_A);
        unsigned short* sB = (unsigned short*)(stg + G2_B);

#pragma unroll
        for (int ks = 0; ks < 2; ks++) {
            int kb = ks * 16 + lko;
            unsigned af[2][4], bf[2][4];
#pragma unroll
            for (int mt = 0; mt < 2; mt++) {
                int r = (wm * 32 + mt * 16 + lrow) * PS + kb;
                ldm4(af[mt], &sA[r]);
            }
#pragma unroll
            for (int nb = 0; nb < 2; nb++) {
                int r = (wn * 32 + nb * 16 + lrow) * PS + kb;
                ldm4(bf[nb], &sB[r]);
            }
            // nt outer, mt inner
#pragma unroll
            for (int nt = 0; nt < 4; nt++) {
                int nb = nt >> 1, o = nt & 1;
#pragma unroll
                for (int mt = 0; mt < 2; mt++)
                    mmah(acc[mt][nt], af[mt], bf[nb][o], bf[nb][o + 2]);
            }
        }
    }

    float* Cp = outp + (size_t)bh * Tt * Dd;
    int rbase = m0 + wm * 32 + (lane >> 2);
    int cbase = n0 + wn * 32 + (lane & 3) * 2;
    float gsc = route[(bh >> 3) * 8 + ((n0 + wn * 32) >> 6)];
    const float* invb = g_inv + (size_t)bh * Tt;
#pragma unroll
    for (int mt = 0; mt < 2; mt++) {
        int r0 = rbase + mt * 16;
        float s0 = gsc * invb[r0];
        float s1 = gsc * invb[r0 + 8];
#pragma unroll
        for (int nt = 0; nt < 4; nt++) {
            int c = cbase + nt * 8;
            *(float2*)&Cp[(size_t)r0       * Dd + c] = make_float2(acc[mt][nt][0] * s0, acc[mt][nt][1] * s0);
            *(float2*)&Cp[(size_t)(r0 + 8) * Dd + c] = make_float2(acc[mt][nt][2] * s1, acc[mt][nt][3] * s1);
        }
    }
}

// ---------------- launch ----------------
extern "C" void kernel_launch(void* const* d_in, const int* in_sizes, int n_in,
                              void* d_out, int out_size) {
    const float* Q     = (const float*)d_in[0];
    const float* K     = (const float*)d_in[1];
    const float* V     = (const float*)d_in[2];
    const float* route = (const float*)d_in[3];
    const int*   mask  = (const int*)d_in[5];
    float* out = (float*)d_out;

    cudaFuncSetAttribute(gemm1, cudaFuncAttributeMaxDynamicSharedMemorySize, G1_SMEM);
    cudaFuncSetAttribute(gemm2, cudaFuncAttributeMaxDynamicSharedMemorySize, G2_SMEM);

    convert_qk<<<QKV_ELEMS / 2048, 256>>>(Q, K, route);
    convert_vt<<<dim3(Tt / 32, Dd / 32, BHn), 256>>>(V);
    convert_mask<<<MASK_ELEMS / 1024, 256>>>(mask);
    gemm1<<<dim3(Tt / 256, Tt / 128, BHn), 512, G1_SMEM>>>();
    make_inv<<<BHn * Tt / 256, 256>>>();
    gemm2<<<dim3(Dd / 128, Tt / 128, BHn), 512, G2_SMEM>>>(out, route);
}

// round 15
// speedup vs baseline: 1.1564x; 1.0204x over previous
#include <cuda_runtime.h>
#include <cuda_fp16.h>
#include <cstdint>

#define Tt 2048
#define Dd 512
#define BHn 16
#define QKV_ELEMS 16777216u
#define MASK_WORDS 131072u          // 2048*2048/32
#define S_ELEMS   67108864u

// ---------------- scratch (device globals) ----------------
__device__ __half g_Qh[QKV_ELEMS];
__device__ __half g_Kh[QKV_ELEMS];
__device__ __half g_Vt[QKV_ELEMS];
__device__ __half g_E [S_ELEMS];            // exp(S-4), masked entries = 0
__device__ unsigned g_Mb[MASK_WORDS];       // bit-packed mask (1 = masked)
__device__ float  g_psum[BHn * Tt * 16];    // per-(row, n-block) partial sums

// ---------------- helpers ----------------
__device__ __forceinline__ void ldm4(unsigned* r, const void* p) {
    unsigned a = (unsigned)__cvta_generic_to_shared(p);
    asm volatile("ldmatrix.sync.aligned.m8n8.x4.shared.b16 {%0,%1,%2,%3}, [%4];"
                 : "=r"(r[0]), "=r"(r[1]), "=r"(r[2]), "=r"(r[3]) : "r"(a));
}
__device__ __forceinline__ void mmah(float* c, const unsigned* a, unsigned b0, unsigned b1) {
    asm volatile(
        "mma.sync.aligned.m16n8k16.row.col.f32.f16.f16.f32 "
        "{%0,%1,%2,%3},{%4,%5,%6,%7},{%8,%9},{%0,%1,%2,%3};\n"
        : "+f"(c[0]), "+f"(c[1]), "+f"(c[2]), "+f"(c[3])
        : "r"(a[0]), "r"(a[1]), "r"(a[2]), "r"(a[3]), "r"(b0), "r"(b1));
}
__device__ __forceinline__ void cpasync16(void* s, const void* g) {
    unsigned sa = (unsigned)__cvta_generic_to_shared(s);
    asm volatile("cp.async.cg.shared.global [%0], [%1], 16;" :: "r"(sa), "l"(g));
}
#define CP_COMMIT() asm volatile("cp.async.commit_group;" ::: "memory")
#define CP_WAIT2()  asm volatile("cp.async.wait_group 2;" ::: "memory")

// FMA-pipe exp2 (no MUFU). Valid for |y| < 2^21; rel err ~1e-5.
__device__ __forceinline__ float fexp2(float y) {
    float z  = __fadd_rn(y, 12582912.0f);
    float nf = __fadd_rn(z, -12582912.0f);
    float f  = y - nf;
    float p  = 0.0096181291f;
    p = fmaf(p, f, 0.0555041087f);
    p = fmaf(p, f, 0.2402265069f);
    p = fmaf(p, f, 0.6931471806f);
    p = fmaf(p, f, 1.0f);
    int nb = __float_as_int(z);
    float s = __int_as_float((nb - (0x4B400000 - 127)) << 23);
    return p * s;
}

// ---------------- convert Q,K to fp16 (gate & 1/sqrt(64) folded into Q) ----------------
__global__ void convert_qk(const float* __restrict__ Q, const float* __restrict__ K,
                           const float* __restrict__ route) {
    unsigned idx = (blockIdx.x * 256u + threadIdx.x) * 2u;    // float4 index (pairs)
#pragma unroll
    for (int u = 0; u < 2; u++) {
        unsigned id4 = idx + u;
        unsigned i = id4 * 4u;
        int d = (int)(i & (Dd - 1));
        int b = (int)(i >> 23);
        float g = route[b * 8 + (d >> 6)] * 0.125f;
        float4 q = ((const float4*)Q)[id4];
        float4 k = ((const float4*)K)[id4];
        __half2 q01 = __floats2half2_rn(q.x * g, q.y * g);
        __half2 q23 = __floats2half2_rn(q.z * g, q.w * g);
        __half2 k01 = __floats2half2_rn(k.x, k.y);
        __half2 k23 = __floats2half2_rn(k.z, k.w);
        ((__half2*)g_Qh)[id4 * 2]     = q01;
        ((__half2*)g_Qh)[id4 * 2 + 1] = q23;
        ((__half2*)g_Kh)[id4 * 2]     = k01;
        ((__half2*)g_Kh)[id4 * 2 + 1] = k23;
    }
}

// ---------------- transpose V -> Vt fp16 ----------------
__global__ void convert_vt(const float* __restrict__ V) {
    __shared__ float tile[32][33];
    int bh = blockIdx.z, t0 = blockIdx.x * 32, d0 = blockIdx.y * 32;
    int tx = threadIdx.x & 31, ty = threadIdx.x >> 5;
    const float* Vb = V + (size_t)bh * Tt * Dd;
#pragma unroll
    for (int j = 0; j < 4; j++)
        tile[ty + j * 8][tx] = Vb[(size_t)(t0 + ty + j * 8) * Dd + d0 + tx];
    __syncthreads();
#pragma unroll
    for (int j = 0; j < 4; j++) {
        int d = d0 + ty + j * 8, tt = t0 + tx;
        g_Vt[(size_t)bh * Dd * Tt + (size_t)d * Tt + tt] = __float2half_rn(tile[tx][ty + j * 8]);
    }
}

// ---------------- mask -> bit-packed (1 = masked) ----------------
__global__ void convert_mask(const int* __restrict__ mask) {
    unsigned w = blockIdx.x * 256u + threadIdx.x;     // word index, 0..131071
    const int4* m4 = (const int4*)(mask + (size_t)w * 32);
    unsigned word = 0;
#pragma unroll
    for (int j = 0; j < 8; j++) {
        int4 m = m4[j];
        word |= (m.x ? 1u : 0u) << (j * 4);
        word |= (m.y ? 1u : 0u) << (j * 4 + 1);
        word |= (m.z ? 1u : 0u) << (j * 4 + 2);
        word |= (m.w ? 1u : 0u) << (j * 4 + 3);
    }
    g_Mb[w] = word;
}

#define PS 40

// ---------------- GEMM1: E = exp(Qg*K^T - 4) masked, + partial row sums ----------------
// CTA 128x256x32, 512 threads
#define G1_A 0
#define G1_B (128 * PS * 2)                 // 10240
#define G1_STAGE (G1_B + 256 * PS * 2)      // 30720
#define NSTAGE 4
#define G1_SMEM (NSTAGE * G1_STAGE)         // 122880

__global__ __launch_bounds__(512, 1) void gemm1() {
    constexpr int lda = Dd, KT = Dd / 32;
    extern __shared__ __align__(16) char sm[];

    const int bh = blockIdx.z;
    const int m0 = blockIdx.y * 128;
    const int n0 = blockIdx.x * 256;
    const int t = threadIdx.x, lane = t & 31, warp = t >> 5;
    const int wm = warp & 3, wn = warp >> 2;     // 4x4 warps, warp tile 32x64
    const int lrow = lane & 15, lko = (lane >> 4) << 3;

    const __half* gA = g_Qh + (size_t)bh * Tt * lda + (size_t)m0 * lda;
    const __half* gB = g_Kh + (size_t)bh * Tt * lda + (size_t)n0 * lda;

    const int arow = t >> 2, kc = t & 3;
    const size_t goff = (size_t)arow * lda + kc * 8;
    const int soff = arow * (PS * 2) + kc * 16;
    const size_t gstep = (size_t)128 * lda;
    const int sstep = 128 * (PS * 2);

    float acc[2][8][4];
#pragma unroll
    for (int a = 0; a < 2; a++)
#pragma unroll
        for (int b = 0; b < 8; b++)
#pragma unroll
            for (int c = 0; c < 4; c++) acc[a][b][c] = 0.f;

#pragma unroll
    for (int p = 0; p < 3; p++) {
        char* stg = sm + p * G1_STAGE;
        const size_t ko = (size_t)p * 32;
        cpasync16(stg + G1_A + soff, gA + goff + ko);
        cpasync16(stg + G1_B + soff, gB + goff + ko);
        cpasync16(stg + G1_B + soff + sstep, gB + goff + gstep + ko);
        CP_COMMIT();
    }

    for (int kt = 0; kt < KT; kt++) {
        CP_WAIT2();
        __syncthreads();
        if (kt + 3 < KT) {
            char* stg = sm + ((kt + 3) & (NSTAGE - 1)) * G1_STAGE;
            const size_t ko = (size_t)(kt + 3) * 32;
            cpasync16(stg + G1_A + soff, gA + goff + ko);
            cpasync16(stg + G1_B + soff, gB + goff + ko);
            cpasync16(stg + G1_B + soff + sstep, gB + goff + gstep + ko);
        }
        CP_COMMIT();

        char* stg = sm + (kt & (NSTAGE - 1)) * G1_STAGE;
        unsigned short* sA = (unsigned short*)(stg + G1_A);
        unsigned short* sB = (unsigned short*)(stg + G1_B);

#pragma unroll
        for (int ks = 0; ks < 2; ks++) {
            int kb = ks * 16 + lko;
            unsigned af[2][4], bf[4][4];
#pragma unroll
            for (int mt = 0; mt < 2; mt++) {
                int r = (wm * 32 + mt * 16 + lrow) * PS + kb;
                ldm4(af[mt], &sA[r]);
            }
#pragma unroll
            for (int nb = 0; nb < 4; nb++) {
                int r = (wn * 64 + nb * 16 + lrow) * PS + kb;
                ldm4(bf[nb], &sB[r]);
            }
#pragma unroll
            for (int nt = 0; nt < 8; nt++) {
                int nb = nt >> 1, o = nt & 1;
#pragma unroll
                for (int mt = 0; mt < 2; mt++)
                    mmah(acc[mt][nt], af[mt], bf[nb][o], bf[nb][o + 2]);
            }
        }
    }

    // epilogue: bit-masked exp(S-4) -> fp16 E, plus per-row partial sums
    const float L2E = 1.44269504f;
    const float SH  = -5.77078016f;
    __half* Ep = g_E + (size_t)bh * Tt * Tt;
    int rbase = m0 + wm * 32 + (lane >> 2);
    int coff  = (lane & 3) * 2;                 // 0,2,4,6 within 64-col span
    int cb0   = n0 + wn * 64;                   // 64-col span base (32-aligned)
    int wbase = cb0 >> 5;                       // word index base within row
    float sums[4] = {0.f, 0.f, 0.f, 0.f};
#pragma unroll
    for (int mt = 0; mt < 2; mt++) {
        int r0 = rbase + mt * 16;
        // two mask words cover cols [cb0, cb0+63] for each row
        unsigned mw0a = g_Mb[(size_t)r0       * (Tt / 32) + wbase];
        unsigned mw0b = g_Mb[(size_t)r0       * (Tt / 32) + wbase + 1];
        unsigned mw1a = g_Mb[(size_t)(r0 + 8) * (Tt / 32) + wbase];
        unsigned mw1b = g_Mb[(size_t)(r0 + 8) * (Tt / 32) + wbase + 1];
#pragma unroll
        for (int nt = 0; nt < 8; nt++) {
            int c = cb0 + coff + nt * 8;
            int bit = (coff + nt * 8) & 31;
            unsigned w0 = ((coff + nt * 8) >> 5) ? mw0b : mw0a;
            unsigned w1 = ((coff + nt * 8) >> 5) ? mw1b : mw1a;
            float e0 = ((w0 >> bit) & 1u)       ? 0.f : fexp2(fmaf(acc[mt][nt][0], L2E, SH));
            float e1 = ((w0 >> (bit + 1)) & 1u) ? 0.f : fexp2(fmaf(acc[mt][nt][1], L2E, SH));
            float e2 = ((w1 >> bit) & 1u)       ? 0.f : fexp2(fmaf(acc[mt][nt][2], L2E, SH));
            float e3 = ((w1 >> (bit + 1)) & 1u) ? 0.f : fexp2(fmaf(acc[mt][nt][3], L2E, SH));
            sums[mt * 2]     += e0 + e1;
            sums[mt * 2 + 1] += e2 + e3;
            *(__half2*)&Ep[(size_t)r0       * Tt + c] = __floats2half2_rn(e0, e1);
            *(__half2*)&Ep[(size_t)(r0 + 8) * Tt + c] = __floats2half2_rn(e2, e3);
        }
    }

    // reduce partial sums: lanes sharing a row, then across wn via smem
    float* ps = (float*)sm;                   // 128 rows x 4 wn
#pragma unroll
    for (int j = 0; j < 4; j++) {
        float v = sums[j];
        v += __shfl_xor_sync(0xFFFFFFFFu, v, 1);
        v += __shfl_xor_sync(0xFFFFFFFFu, v, 2);
        sums[j] = v;
    }
    __syncthreads();
    if ((lane & 3) == 0) {
        int rl = wm * 32 + (lane >> 2);
#pragma unroll
        for (int j = 0; j < 4; j++)
            ps[(rl + j * 8) * 4 + wn] = sums[j];
    }
    __syncthreads();
    if (t < 128) {
        float s4 = ps[t * 4] + ps[t * 4 + 1] + ps[t * 4 + 2] + ps[t * 4 + 3];
        g_psum[((size_t)bh * Tt + m0 + t) * 16 + blockIdx.x] = s4;
    }
}

// ---------------- GEMM2: out = (E * Vt^T) * inv[row] * gate, CTA 128x128x32 ----------------
// inv computed in prologue from g_psum (no separate make_inv kernel)
#define G2_A 0
#define G2_B (128 * PS * 2)
#define G2_STAGE (2 * 128 * PS * 2)          // 20480
#define G2_SMEM (NSTAGE * G2_STAGE + 512)    // stages + invs[128]

__global__ __launch_bounds__(512, 1) void gemm2(float* __restrict__ outp,
                                                const float* __restrict__ route) {
    constexpr int lda = Tt, KT = Tt / 32;
    extern __shared__ __align__(16) char sm[];
    float* invs = (float*)(sm + NSTAGE * G2_STAGE);   // 128 floats

    const int bh = blockIdx.z;
    const int m0 = blockIdx.y * 128;
    const int n0 = blockIdx.x * 128;
    const int t = threadIdx.x, lane = t & 31, warp = t >> 5;
    const int wm = warp & 3, wn = warp >> 2;     // 4x4 warps, warp tile 32x32
    const int lrow = lane & 15, lko = (lane >> 4) << 3;

    const __half* gA = g_E  + (size_t)bh * Tt * lda + (size_t)m0 * lda;
    const __half* gB = g_Vt + (size_t)bh * Dd * lda + (size_t)n0 * lda;

    const int arow = t >> 2, kc = t & 3;
    const size_t goff = (size_t)arow * lda + kc * 8;
    const int soff = arow * (PS * 2) + kc * 16;

    float acc[2][4][4];
#pragma unroll
    for (int a = 0; a < 2; a++)
#pragma unroll
        for (int b = 0; b < 4; b++)
#pragma unroll
            for (int c = 0; c < 4; c++) acc[a][b][c] = 0.f;

#pragma unroll
    for (int p = 0; p < 3; p++) {
        char* stg = sm + p * G2_STAGE;
        const size_t ko = (size_t)p * 32;
        cpasync16(stg + G2_A + soff, gA + goff + ko);
        cpasync16(stg + G2_B + soff, gB + goff + ko);
        CP_COMMIT();
    }

    // prologue: per-row 1/sum from the 16 gemm1 partials (ordered by kt=0 barrier)
    if (t < 128) {
        const float4* p = (const float4*)&g_psum[((size_t)bh * Tt + m0 + t) * 16];
        float4 a = p[0], b = p[1], c = p[2], d = p[3];
        float tot = (((a.x + a.y) + (a.z + a.w)) + ((b.x + b.y) + (b.z + b.w)))
                  + (((c.x + c.y) + (c.z + c.w)) + ((d.x + d.y) + (d.z + d.w)));
        invs[t] = tot > 0.f ? 1.f / tot : 0.f;
    }

    for (int kt = 0; kt < KT; kt++) {
        CP_WAIT2();
        __syncthreads();
        if (kt + 3 < KT) {
            char* stg = sm + ((kt + 3) & (NSTAGE - 1)) * G2_STAGE;
            const size_t ko = (size_t)(kt + 3) * 32;
            cpasync16(stg + G2_A + soff, gA + goff + ko);
            cpasync16(stg + G2_B + soff, gB + goff + ko);
        }
        CP_COMMIT();

        char* stg = sm + (kt & (NSTAGE - 1)) * G2_STAGE;
        unsigned short* sA = (unsigned short*)(stg + G2_A);
        unsigned short* sB = (unsigned short*)(stg + G2_B);

#pragma unroll
        for (int ks = 0; ks < 2; ks++) {
            int kb = ks * 16 + lko;
            unsigned af[2][4], bf[2][4];
#pragma unroll
            for (int mt = 0; mt < 2; mt++) {
                int r = (wm * 32 + mt * 16 + lrow) * PS + kb;
                ldm4(af[mt], &sA[r]);
            }
#pragma unroll
            for (int nb = 0; nb < 2; nb++) {
                int r = (wn * 32 + nb * 16 + lrow) * PS + kb;
                ldm4(bf[nb], &sB[r]);
            }
#pragma unroll
            for (int nt = 0; nt < 4; nt++) {
                int nb = nt >> 1, o = nt & 1;
#pragma unroll
                for (int mt = 0; mt < 2; mt++)
                    mmah(acc[mt][nt], af[mt], bf[nb][o], bf[nb][o + 2]);
            }
        }
    }

    float* Cp = outp + (size_t)bh * Tt * Dd;
    int rbase = m0 + wm * 32 + (lane >> 2);
    int cbase = n0 + wn * 32 + (lane & 3) * 2;
    float gsc = route[(bh >> 3) * 8 + ((n0 + wn * 32) >> 6)];
#pragma unroll
    for (int mt = 0; mt < 2; mt++) {
        int r0 = rbase + mt * 16;
        float s0 = gsc * invs[r0 - m0];
        float s1 = gsc * invs[r0 - m0 + 8];
#pragma unroll
        for (int nt = 0; nt < 4; nt++) {
            int c = cbase + nt * 8;
            *(float2*)&Cp[(size_t)r0       * Dd + c] = make_float2(acc[mt][nt][0] * s0, acc[mt][nt][1] * s0);
            *(float2*)&Cp[(size_t)(r0 + 8) * Dd + c] = make_float2(acc[mt][nt][2] * s1, acc[mt][nt][3] * s1);
        }
    }
}

// ---------------- launch ----------------
extern "C" void kernel_launch(void* const* d_in, const int* in_sizes, int n_in,
                              void* d_out, int out_size) {
    const float* Q     = (const float*)d_in[0];
    const float* K     = (const float*)d_in[1];
    const float* V     = (const float*)d_in[2];
    const float* route = (const float*)d_in[3];
    const int*   mask  = (const int*)d_in[5];
    float* out = (float*)d_out;

    cudaFuncSetAttribute(gemm1, cudaFuncAttributeMaxDynamicSharedMemorySize, G1_SMEM);
    cudaFuncSetAttribute(gemm2, cudaFuncAttributeMaxDynamicSharedMemorySize, G2_SMEM);

    convert_qk<<<QKV_ELEMS / 2048, 256>>>(Q, K, route);
    convert_vt<<<dim3(Tt / 32, Dd / 32, BHn), 256>>>(V);
    convert_mask<<<MASK_WORDS / 256, 256>>>(mask);
    gemm1<<<dim3(Tt / 256, Tt / 128, BHn), 512, G1_SMEM>>>();
    gemm2<<<dim3(Dd / 128, Tt / 128, BHn), 512, G2_SMEM>>>(out, route);
}